// round 1
// baseline (speedup 1.0000x reference)
#include <cuda_runtime.h>
#include <math.h>

#define LAMDA 0.1f
#define T_AVG 8192

// Global accumulators: [0] = sum (input-target)^2, [1] = sum cyclic diff^2
__device__ float g_acc[2];

__global__ void init_acc_kernel() {
    g_acc[0] = 0.0f;
    g_acc[1] = 0.0f;
}

__global__ void __launch_bounds__(256) reduce_kernel(
    const float4* __restrict__ in,
    const float4* __restrict__ tg,
    int n4, int lim4 /* = n4 - T/4 */)
{
    float s_mse = 0.0f;
    float s_cyc = 0.0f;
    const int t4 = T_AVG / 4;
    const int stride = gridDim.x * blockDim.x;

    for (int i = blockIdx.x * blockDim.x + threadIdx.x; i < n4; i += stride) {
        float4 a = in[i];
        float4 b = tg[i];
        float d0 = a.x - b.x;
        float d1 = a.y - b.y;
        float d2 = a.z - b.z;
        float d3 = a.w - b.w;
        s_mse += d0 * d0;
        s_mse += d1 * d1;
        s_mse += d2 * d2;
        s_mse += d3 * d3;
        if (i < lim4) {
            float4 c = in[i + t4];
            float e0 = a.x - c.x;
            float e1 = a.y - c.y;
            float e2 = a.z - c.z;
            float e3 = a.w - c.w;
            s_cyc += e0 * e0;
            s_cyc += e1 * e1;
            s_cyc += e2 * e2;
            s_cyc += e3 * e3;
        }
    }

    // Warp reduction
    #pragma unroll
    for (int off = 16; off > 0; off >>= 1) {
        s_mse += __shfl_xor_sync(0xffffffffu, s_mse, off);
        s_cyc += __shfl_xor_sync(0xffffffffu, s_cyc, off);
    }

    __shared__ float sm_mse[8];
    __shared__ float sm_cyc[8];
    int wid = threadIdx.x >> 5;
    int lid = threadIdx.x & 31;
    if (lid == 0) {
        sm_mse[wid] = s_mse;
        sm_cyc[wid] = s_cyc;
    }
    __syncthreads();

    if (wid == 0) {
        float bm = (lid < 8) ? sm_mse[lid] : 0.0f;
        float bc = (lid < 8) ? sm_cyc[lid] : 0.0f;
        #pragma unroll
        for (int off = 4; off > 0; off >>= 1) {
            bm += __shfl_xor_sync(0xffffffffu, bm, off);
            bc += __shfl_xor_sync(0xffffffffu, bc, off);
        }
        if (lid == 0) {
            atomicAdd(&g_acc[0], bm);
            atomicAdd(&g_acc[1], bc);
        }
    }
}

__global__ void final_kernel(float* __restrict__ out, float inv_n, int nSteps) {
    float l1 = (nSteps != 1) ? (LAMDA * sqrtf(g_acc[1])) : 0.0f;
    out[0] = g_acc[0] * inv_n + l1;
}

extern "C" void kernel_launch(void* const* d_in, const int* in_sizes, int n_in,
                              void* d_out, int out_size) {
    const float* input  = (const float*)d_in[0];
    const float* target = (const float*)d_in[1];
    float* out = (float*)d_out;

    int n = in_sizes[0];         // 16,777,216
    int n4 = n / 4;
    int T = T_AVG;               // 8192 (fixed for this problem)
    int nSteps = n / T;          // 2048
    int lim4 = n4 - T / 4;       // (N-1)*T / 4

    init_acc_kernel<<<1, 1>>>();

    const int threads = 256;
    const int blocks = 148 * 8;  // 1184 blocks, ~14 float4 per thread
    reduce_kernel<<<blocks, threads>>>(
        (const float4*)input, (const float4*)target, n4, lim4);

    final_kernel<<<1, 1>>>(out, 1.0f / (float)n, nSteps);
}

// round 2
// speedup vs baseline: 1.0767x; 1.0767x over previous
#include <cuda_runtime.h>
#include <math.h>

#define LAMDA 0.1f
#define T_AVG 8192

// Accumulators: zero at module load; reset by the last block each launch,
// so every graph replay starts clean. Counter self-wraps via atomicInc.
__device__ float g_acc0;
__device__ float g_acc1;
__device__ unsigned int g_count;

__global__ void __launch_bounds__(256) fused_loss_kernel(
    const float4* __restrict__ in,
    const float4* __restrict__ tg,
    float* __restrict__ out,
    int n4, int lim4 /* = n4 - T/4 */,
    float inv_n, int nSteps)
{
    float s_mse = 0.0f;
    float s_cyc = 0.0f;
    const int t4 = T_AVG / 4;
    const int stride = gridDim.x * blockDim.x;

    #pragma unroll 4
    for (int i = blockIdx.x * blockDim.x + threadIdx.x; i < n4; i += stride) {
        float4 a = in[i];
        float4 b = tg[i];
        float d0 = a.x - b.x;
        float d1 = a.y - b.y;
        float d2 = a.z - b.z;
        float d3 = a.w - b.w;
        s_mse += d0 * d0 + d1 * d1 + d2 * d2 + d3 * d3;
        if (i < lim4) {
            float4 c = in[i + t4];
            float e0 = a.x - c.x;
            float e1 = a.y - c.y;
            float e2 = a.z - c.z;
            float e3 = a.w - c.w;
            s_cyc += e0 * e0 + e1 * e1 + e2 * e2 + e3 * e3;
        }
    }

    // Warp reduction
    #pragma unroll
    for (int off = 16; off > 0; off >>= 1) {
        s_mse += __shfl_xor_sync(0xffffffffu, s_mse, off);
        s_cyc += __shfl_xor_sync(0xffffffffu, s_cyc, off);
    }

    __shared__ float sm_mse[8];
    __shared__ float sm_cyc[8];
    int wid = threadIdx.x >> 5;
    int lid = threadIdx.x & 31;
    if (lid == 0) {
        sm_mse[wid] = s_mse;
        sm_cyc[wid] = s_cyc;
    }
    __syncthreads();

    if (threadIdx.x == 0) {
        float bm = sm_mse[0];
        float bc = sm_cyc[0];
        #pragma unroll
        for (int w = 1; w < 8; w++) {
            bm += sm_mse[w];
            bc += sm_cyc[w];
        }
        atomicAdd(&g_acc0, bm);
        atomicAdd(&g_acc1, bc);
        __threadfence();
        // atomicInc wraps to 0 when old == gridDim.x-1 -> self-resetting counter
        unsigned int ticket = atomicInc(&g_count, gridDim.x - 1);
        if (ticket == gridDim.x - 1) {
            // Read through the atomic path (L2) to avoid any stale L1 view.
            float tot_mse = atomicAdd(&g_acc0, 0.0f);
            float tot_cyc = atomicAdd(&g_acc1, 0.0f);
            float l1 = (nSteps != 1) ? (LAMDA * sqrtf(tot_cyc)) : 0.0f;
            out[0] = tot_mse * inv_n + l1;
            // Reset for next graph replay.
            g_acc0 = 0.0f;
            g_acc1 = 0.0f;
        }
    }
}

extern "C" void kernel_launch(void* const* d_in, const int* in_sizes, int n_in,
                              void* d_out, int out_size) {
    const float* input  = (const float*)d_in[0];
    const float* target = (const float*)d_in[1];
    float* out = (float*)d_out;

    int n = in_sizes[0];         // 16,777,216
    int n4 = n / 4;
    int T = T_AVG;               // 8192 (fixed for this problem)
    int nSteps = n / T;          // 2048
    int lim4 = n4 - T / 4;       // (N-1)*T / 4

    const int threads = 256;
    const int blocks = 148 * 16; // 2368 blocks, ~7 float4 per thread
    fused_loss_kernel<<<blocks, threads>>>(
        (const float4*)input, (const float4*)target, out,
        n4, lim4, 1.0f / (float)n, nSteps);
}

// round 3
// speedup vs baseline: 1.0780x; 1.0012x over previous
#include <cuda_runtime.h>
#include <math.h>

#define LAMDA 0.1f
#define T_AVG 8192

// Accumulators: zero at module load; reset by the last block each launch,
// so every graph replay starts clean. Counter self-wraps via atomicInc.
__device__ float g_acc0;
__device__ float g_acc1;
__device__ unsigned int g_count;

__device__ __forceinline__ float sq4(float4 a, float4 b) {
    float d0 = a.x - b.x;
    float d1 = a.y - b.y;
    float d2 = a.z - b.z;
    float d3 = a.w - b.w;
    return d0 * d0 + d1 * d1 + d2 * d2 + d3 * d3;
}

__global__ void __launch_bounds__(256) fused_loss_kernel(
    const float4* __restrict__ in,
    const float4* __restrict__ tg,
    float* __restrict__ out,
    int n4, int lim4 /* = n4 - T/4 */,
    float inv_n, int nSteps)
{
    float s_mse = 0.0f;
    float s_cyc = 0.0f;
    const int t4 = T_AVG / 4;
    const int stride = gridDim.x * blockDim.x;
    int i = blockIdx.x * blockDim.x + threadIdx.x;

    // Main 4x-unrolled path: front-batch 12 independent LDG.128s.
    // Only valid while the whole batch is < lim4 (cyc predicate uniform-true).
    for (; i + 3 * stride < lim4; i += 4 * stride) {
        int i0 = i, i1 = i + stride, i2 = i + 2 * stride, i3 = i + 3 * stride;
        float4 a0 = in[i0], a1 = in[i1], a2 = in[i2], a3 = in[i3];
        float4 b0 = tg[i0], b1 = tg[i1], b2 = tg[i2], b3 = tg[i3];
        float4 c0 = in[i0 + t4], c1 = in[i1 + t4], c2 = in[i2 + t4], c3 = in[i3 + t4];
        s_mse += sq4(a0, b0);
        s_mse += sq4(a1, b1);
        s_mse += sq4(a2, b2);
        s_mse += sq4(a3, b3);
        s_cyc += sq4(a0, c0);
        s_cyc += sq4(a1, c1);
        s_cyc += sq4(a2, c2);
        s_cyc += sq4(a3, c3);
    }

    // Remainder: per-element predicate on the cyclic term.
    for (; i < n4; i += stride) {
        float4 a = in[i];
        float4 b = tg[i];
        s_mse += sq4(a, b);
        if (i < lim4) {
            float4 c = in[i + t4];
            s_cyc += sq4(a, c);
        }
    }

    // Warp reduction
    #pragma unroll
    for (int off = 16; off > 0; off >>= 1) {
        s_mse += __shfl_xor_sync(0xffffffffu, s_mse, off);
        s_cyc += __shfl_xor_sync(0xffffffffu, s_cyc, off);
    }

    __shared__ float sm_mse[8];
    __shared__ float sm_cyc[8];
    int wid = threadIdx.x >> 5;
    int lid = threadIdx.x & 31;
    if (lid == 0) {
        sm_mse[wid] = s_mse;
        sm_cyc[wid] = s_cyc;
    }
    __syncthreads();

    if (threadIdx.x == 0) {
        float bm = sm_mse[0];
        float bc = sm_cyc[0];
        #pragma unroll
        for (int w = 1; w < 8; w++) {
            bm += sm_mse[w];
            bc += sm_cyc[w];
        }
        atomicAdd(&g_acc0, bm);
        atomicAdd(&g_acc1, bc);
        __threadfence();
        // atomicInc wraps to 0 when old == gridDim.x-1 -> self-resetting counter
        unsigned int ticket = atomicInc(&g_count, gridDim.x - 1);
        if (ticket == gridDim.x - 1) {
            float tot_mse = atomicAdd(&g_acc0, 0.0f);
            float tot_cyc = atomicAdd(&g_acc1, 0.0f);
            float l1 = (nSteps != 1) ? (LAMDA * sqrtf(tot_cyc)) : 0.0f;
            out[0] = tot_mse * inv_n + l1;
            // Reset for next graph replay.
            g_acc0 = 0.0f;
            g_acc1 = 0.0f;
        }
    }
}

extern "C" void kernel_launch(void* const* d_in, const int* in_sizes, int n_in,
                              void* d_out, int out_size) {
    const float* input  = (const float*)d_in[0];
    const float* target = (const float*)d_in[1];
    float* out = (float*)d_out;

    int n = in_sizes[0];         // 16,777,216
    int n4 = n / 4;
    int T = T_AVG;               // 8192 (fixed for this problem)
    int nSteps = n / T;          // 2048
    int lim4 = n4 - T / 4;       // (N-1)*T / 4

    const int threads = 256;
    const int blocks = 148 * 8;  // 1184 blocks = 2048 threads/SM, single wave
    fused_loss_kernel<<<blocks, threads>>>(
        (const float4*)input, (const float4*)target, out,
        n4, lim4, 1.0f / (float)n, nSteps);
}

// round 4
// speedup vs baseline: 1.0948x; 1.0156x over previous
#include <cuda_runtime.h>
#include <math.h>

#define LAMDA 0.1f
#define T_AVG 8192
#define UNROLL 6

// Accumulators: zero at module load; reset by the last block each launch,
// so every graph replay starts clean. Counter self-wraps via atomicInc.
__device__ float g_acc0;
__device__ float g_acc1;
__device__ unsigned int g_count;

__device__ __forceinline__ float sq4(float4 a, float4 b) {
    float d0 = a.x - b.x;
    float d1 = a.y - b.y;
    float d2 = a.z - b.z;
    float d3 = a.w - b.w;
    return d0 * d0 + d1 * d1 + d2 * d2 + d3 * d3;
}

__global__ void __launch_bounds__(256, 4) fused_loss_kernel(
    const float4* __restrict__ in,
    const float4* __restrict__ tg,
    float* __restrict__ out,
    int n4, int lim4 /* = n4 - T/4 */,
    float inv_n, int nSteps)
{
    float s_mse = 0.0f;
    float s_cyc = 0.0f;
    const int t4 = T_AVG / 4;
    const int stride = gridDim.x * blockDim.x;
    int i = blockIdx.x * blockDim.x + threadIdx.x;

    // Main UNROLLx path: front-batch 3*UNROLL independent LDG.128s.
    // Valid while the whole batch is < lim4 (cyc predicate uniform-true).
    for (; i + (UNROLL - 1) * stride < lim4; i += UNROLL * stride) {
        float4 a[UNROLL], b[UNROLL], c[UNROLL];
        #pragma unroll
        for (int u = 0; u < UNROLL; u++) a[u] = in[i + u * stride];
        #pragma unroll
        for (int u = 0; u < UNROLL; u++) c[u] = in[i + u * stride + t4];
        #pragma unroll
        for (int u = 0; u < UNROLL; u++) b[u] = tg[i + u * stride];
        #pragma unroll
        for (int u = 0; u < UNROLL; u++) {
            s_mse += sq4(a[u], b[u]);
            s_cyc += sq4(a[u], c[u]);
        }
    }

    // Remainder: per-element predicate on the cyclic term.
    for (; i < n4; i += stride) {
        float4 a = in[i];
        float4 b = tg[i];
        s_mse += sq4(a, b);
        if (i < lim4) {
            float4 c = in[i + t4];
            s_cyc += sq4(a, c);
        }
    }

    // Warp reduction
    #pragma unroll
    for (int off = 16; off > 0; off >>= 1) {
        s_mse += __shfl_xor_sync(0xffffffffu, s_mse, off);
        s_cyc += __shfl_xor_sync(0xffffffffu, s_cyc, off);
    }

    __shared__ float sm_mse[8];
    __shared__ float sm_cyc[8];
    int wid = threadIdx.x >> 5;
    int lid = threadIdx.x & 31;
    if (lid == 0) {
        sm_mse[wid] = s_mse;
        sm_cyc[wid] = s_cyc;
    }
    __syncthreads();

    if (threadIdx.x == 0) {
        float bm = sm_mse[0];
        float bc = sm_cyc[0];
        #pragma unroll
        for (int w = 1; w < 8; w++) {
            bm += sm_mse[w];
            bc += sm_cyc[w];
        }
        atomicAdd(&g_acc0, bm);
        atomicAdd(&g_acc1, bc);
        __threadfence();
        // atomicInc wraps to 0 when old == gridDim.x-1 -> self-resetting counter
        unsigned int ticket = atomicInc(&g_count, gridDim.x - 1);
        if (ticket == gridDim.x - 1) {
            float tot_mse = atomicAdd(&g_acc0, 0.0f);
            float tot_cyc = atomicAdd(&g_acc1, 0.0f);
            float l1 = (nSteps != 1) ? (LAMDA * sqrtf(tot_cyc)) : 0.0f;
            out[0] = tot_mse * inv_n + l1;
            // Reset for next graph replay.
            g_acc0 = 0.0f;
            g_acc1 = 0.0f;
        }
    }
}

extern "C" void kernel_launch(void* const* d_in, const int* in_sizes, int n_in,
                              void* d_out, int out_size) {
    const float* input  = (const float*)d_in[0];
    const float* target = (const float*)d_in[1];
    float* out = (float*)d_out;

    int n = in_sizes[0];         // 16,777,216
    int n4 = n / 4;
    int T = T_AVG;               // 8192 (fixed for this problem)
    int nSteps = n / T;          // 2048
    int lim4 = n4 - T / 4;       // (N-1)*T / 4

    const int threads = 256;
    const int blocks = 148 * 4;  // 592 blocks = 1024 threads/SM, 64-reg budget
    fused_loss_kernel<<<blocks, threads>>>(
        (const float4*)input, (const float4*)target, out,
        n4, lim4, 1.0f / (float)n, nSteps);
}

// round 5
// speedup vs baseline: 1.7273x; 1.5777x over previous
#include <cuda_runtime.h>
#include <math.h>

#define LAMDA 0.1f
#define T_AVG 8192
#define THREADS 256
#define BLOCKS (148 * 4)

// Accumulators: zero at module load; reset by the last block each launch,
// so every graph replay starts clean. Counter self-wraps via atomicInc.
__device__ float g_acc0;
__device__ float g_acc1;
__device__ unsigned int g_count;

__device__ __forceinline__ float sq4(float4 a, float4 b) {
    float d0 = a.x - b.x;
    float d1 = a.y - b.y;
    float d2 = a.z - b.z;
    float d3 = a.w - b.w;
    return d0 * d0 + d1 * d1 + d2 * d2 + d3 * d3;
}

__global__ void __launch_bounds__(THREADS, 4) fused_loss_kernel(
    const float4* __restrict__ in,
    const float4* __restrict__ tg,
    float* __restrict__ out,
    int n4, int lim4 /* = n4 - T/4 */, int chunk,
    float inv_n, int nSteps)
{
    float s_mse = 0.0f;
    float s_cyc = 0.0f;
    const int t4 = T_AVG / 4;

    // Per-block contiguous tile: [base, end). Block-stride = THREADS float4 = 4KB.
    // The c-read (i + 32KB) is the first DRAM touch; when the a-front reaches
    // that address ~8 iterations later the line is still in L1 (96KB window).
    const int base = blockIdx.x * chunk;
    const int end = min(base + chunk, n4);
    const int end_cyc = min(end, lim4);
    int i = base + threadIdx.x;

    // Main 4x-unrolled path (both terms, 12 front-batched LDG.128s).
    for (; i + 3 * THREADS < end_cyc; i += 4 * THREADS) {
        float4 a0 = in[i];
        float4 a1 = in[i + THREADS];
        float4 a2 = in[i + 2 * THREADS];
        float4 a3 = in[i + 3 * THREADS];
        float4 c0 = in[i + t4];
        float4 c1 = in[i + THREADS + t4];
        float4 c2 = in[i + 2 * THREADS + t4];
        float4 c3 = in[i + 3 * THREADS + t4];
        float4 b0 = __ldcs(&tg[i]);
        float4 b1 = __ldcs(&tg[i + THREADS]);
        float4 b2 = __ldcs(&tg[i + 2 * THREADS]);
        float4 b3 = __ldcs(&tg[i + 3 * THREADS]);
        s_mse += sq4(a0, b0);
        s_mse += sq4(a1, b1);
        s_mse += sq4(a2, b2);
        s_mse += sq4(a3, b3);
        s_cyc += sq4(a0, c0);
        s_cyc += sq4(a1, c1);
        s_cyc += sq4(a2, c2);
        s_cyc += sq4(a3, c3);
    }
    // Tail of the cyc region.
    for (; i < end_cyc; i += THREADS) {
        float4 a = in[i];
        float4 b = __ldcs(&tg[i]);
        float4 c = in[i + t4];
        s_mse += sq4(a, b);
        s_cyc += sq4(a, c);
    }
    // MSE-only region (last T elements; only the final block(s) see this).
    for (; i < end; i += THREADS) {
        float4 a = in[i];
        float4 b = __ldcs(&tg[i]);
        s_mse += sq4(a, b);
    }

    // Warp reduction
    #pragma unroll
    for (int off = 16; off > 0; off >>= 1) {
        s_mse += __shfl_xor_sync(0xffffffffu, s_mse, off);
        s_cyc += __shfl_xor_sync(0xffffffffu, s_cyc, off);
    }

    __shared__ float sm_mse[8];
    __shared__ float sm_cyc[8];
    int wid = threadIdx.x >> 5;
    int lid = threadIdx.x & 31;
    if (lid == 0) {
        sm_mse[wid] = s_mse;
        sm_cyc[wid] = s_cyc;
    }
    __syncthreads();

    if (threadIdx.x == 0) {
        float bm = sm_mse[0];
        float bc = sm_cyc[0];
        #pragma unroll
        for (int w = 1; w < 8; w++) {
            bm += sm_mse[w];
            bc += sm_cyc[w];
        }
        atomicAdd(&g_acc0, bm);
        atomicAdd(&g_acc1, bc);
        __threadfence();
        // atomicInc wraps to 0 when old == gridDim.x-1 -> self-resetting counter
        unsigned int ticket = atomicInc(&g_count, gridDim.x - 1);
        if (ticket == gridDim.x - 1) {
            float tot_mse = atomicAdd(&g_acc0, 0.0f);
            float tot_cyc = atomicAdd(&g_acc1, 0.0f);
            float l1 = (nSteps != 1) ? (LAMDA * sqrtf(tot_cyc)) : 0.0f;
            out[0] = tot_mse * inv_n + l1;
            // Reset for next graph replay.
            g_acc0 = 0.0f;
            g_acc1 = 0.0f;
        }
    }
}

extern "C" void kernel_launch(void* const* d_in, const int* in_sizes, int n_in,
                              void* d_out, int out_size) {
    const float* input  = (const float*)d_in[0];
    const float* target = (const float*)d_in[1];
    float* out = (float*)d_out;

    int n = in_sizes[0];         // 16,777,216
    int n4 = n / 4;
    int T = T_AVG;               // 8192 (fixed for this problem)
    int nSteps = n / T;          // 2048
    int lim4 = n4 - T / 4;       // (N-1)*T / 4

    // Contiguous per-block chunk, rounded up to the block stride so every
    // block except the last iterates uniformly.
    int chunk = (n4 + BLOCKS - 1) / BLOCKS;
    chunk = (chunk + THREADS - 1) / THREADS * THREADS;

    fused_loss_kernel<<<BLOCKS, THREADS>>>(
        (const float4*)input, (const float4*)target, out,
        n4, lim4, chunk, 1.0f / (float)n, nSteps);
}